// round 9
// baseline (speedup 1.0000x reference)
#include <cuda_runtime.h>
#include <cuda_fp16.h>
#include <cstdint>

// ---------------------------------------------------------------------------
// Problem constants
// ---------------------------------------------------------------------------
#define BDIM   16
#define FH     32
#define FW     32
#define NBOX   16
#define CCH    256     // conv out channels
#define DDIM   256     // dense out
#define KDIM   768     // 16*16*3
#define M_TOT  16384   // B*32*32
#define S_ROI  7

// Scratch (static __device__ — no allocations allowed)
__device__ __half g_Wh[CCH * KDIM];          // W transposed+f16: [256 n][768 k]
__device__ __half g_feat[M_TOT * CCH];       // conv+relu feat [16384, 256] f16

// ---------------------------------------------------------------------------
// helpers
// ---------------------------------------------------------------------------
__device__ __forceinline__ uint32_t smem_to_u32(const void* smem_ptr) {
    uint32_t addr;
    asm("{ .reg .u64 tmp; cvta.to.shared.u64 tmp, %1; cvt.u32.u64 %0, tmp; }"
        : "=r"(addr) : "l"(smem_ptr));
    return addr;
}
__device__ __forceinline__ uint32_t f2h2(float lo, float hi) {
    uint32_t r;
    asm("cvt.rn.f16x2.f32 %0, %1, %2;" : "=r"(r) : "f"(hi), "f"(lo));
    return r;
}
__device__ __forceinline__ void mma_f16(float* d, const uint32_t* a, const uint32_t* b) {
    asm volatile(
        "mma.sync.aligned.m16n8k16.row.col.f32.f16.f16.f32 "
        "{%0,%1,%2,%3}, {%4,%5,%6,%7}, {%8,%9}, {%0,%1,%2,%3};"
        : "+f"(d[0]), "+f"(d[1]), "+f"(d[2]), "+f"(d[3])
        : "r"(a[0]), "r"(a[1]), "r"(a[2]), "r"(a[3]), "r"(b[0]), "r"(b[1]));
}
__device__ __forceinline__ void cp16(uint32_t smem_dst, const void* gsrc) {
    asm volatile("cp.async.cg.shared.global [%0], [%1], 16;"
                 :: "r"(smem_dst), "l"(gsrc));
}
#define CP_COMMIT() asm volatile("cp.async.commit_group;" ::: "memory")
#define CP_WAIT1()  asm volatile("cp.async.wait_group 1;"  ::: "memory")
#define CP_WAIT0()  asm volatile("cp.async.wait_group 0;"  ::: "memory")

// ---------------------------------------------------------------------------
// 0) W prepass: W[768,256] f32 -> g_Wh[256 n][768 k] f16 (transpose+convert)
// ---------------------------------------------------------------------------
__global__ __launch_bounds__(256) void wprep_kernel(const float* __restrict__ W) {
    __shared__ float t[32][33];
    int kb = blockIdx.x * 32, nb = blockIdx.y * 32;
    int tx = threadIdx.x & 31, ty = threadIdx.x >> 5;   // 32 x 8
    #pragma unroll
    for (int i = 0; i < 32; i += 8)
        t[ty + i][tx] = W[(kb + ty + i) * CCH + nb + tx];
    __syncthreads();
    #pragma unroll
    for (int i = 0; i < 32; i += 8)
        g_Wh[(nb + ty + i) * KDIM + kb + tx] = __float2half_rn(t[tx][ty + i]);
}

// ---------------------------------------------------------------------------
// 1) Conv-as-GEMM, fused im2col, fp16 m16n8k16 mma, 3-stage cp.async,
//    single barrier per chunk. CTA tile 128x128, 8 warps each 64x32.
// ---------------------------------------------------------------------------
#define BK      32
#define NCH     (KDIM / BK)          // 24
#define LDA     40                   // floats per A row (32 data + 8 pad)
#define LDBT    40                   // halves per B row (32 data + 8 pad)
#define A_BYTES (128 * LDA * 4)      // 20480
#define B_BYTES (128 * LDBT * 2)     // 10240
#define STG_BYTES (A_BYTES + B_BYTES)// 30720
#define STAGES  3
#define SMEM_BYTES (STAGES * STG_BYTES)   // 92160

__global__ __launch_bounds__(256, 2) void conv_mma_kernel(
    const float* __restrict__ img,     // [16,512,512,3]
    const float* __restrict__ bias)    // [256]
{
    extern __shared__ float smem[];
    const uint32_t sb = smem_to_u32(smem);

    const int tid = threadIdx.x;
    const int wid = tid >> 5;
    const int lid = tid & 31;
    const int g   = lid >> 2;          // 0..7
    const int t4  = lid & 3;           // 0..3
    const int wm  = wid & 1;           // 2 warps in M
    const int wn  = wid >> 1;          // 4 warps in N

    const int n0 = blockIdx.x * 128;
    const int m0 = blockIdx.y * 128;

    // cp.async source bases
    const float* aBase[4];
    #pragma unroll
    for (int i = 0; i < 4; i++) {
        int f4  = tid + i * 256;               // 0..1023
        int row = f4 >> 3;                     // 0..127
        int m   = m0 + row;
        int b   = m >> 10;
        int oy  = (m >> 5) & 31;
        int ox  = m & 31;
        aBase[i] = img + (size_t)((b * 512 + oy * 16) * 512 + ox * 16) * 3;
    }
    const __half* bBase[2];
    #pragma unroll
    for (int i = 0; i < 2; i++) {
        int f4  = tid + i * 256;               // 0..511
        int row = f4 >> 2;                     // 0..127
        int q   = f4 & 3;
        bBase[i] = g_Wh + (size_t)(n0 + row) * KDIM + q * 8;
    }

    auto issue = [&](int c) {
        const int k0 = c * BK;
        const uint32_t soff = sb + (uint32_t)(c % STAGES) * STG_BYTES;
        #pragma unroll
        for (int i = 0; i < 4; i++) {
            int f4  = tid + i * 256;
            int row = f4 >> 3;
            int q   = f4 & 7;
            int k   = k0 + q * 4;
            int ky  = k / 48;
            int rem = k - ky * 48;             // 4 | 48 -> never crosses pixel run
            cp16(soff + (uint32_t)(row * (LDA * 4) + q * 16),
                 aBase[i] + ky * 1536 + rem);
        }
        #pragma unroll
        for (int i = 0; i < 2; i++) {
            int f4  = tid + i * 256;
            int row = f4 >> 2;
            int q   = f4 & 3;
            cp16(soff + (uint32_t)(A_BYTES + row * (LDBT * 2) + q * 16),
                 bBase[i] + k0);
        }
        CP_COMMIT();
    };

    float acc[4][4][4];
    #pragma unroll
    for (int i = 0; i < 4; i++)
        #pragma unroll
        for (int j = 0; j < 4; j++)
            #pragma unroll
            for (int r = 0; r < 4; r++) acc[i][j][r] = 0.f;

    // prologue: 2 chunks in flight
    issue(0); issue(1);

    for (int c = 0; c < NCH; c++) {
        if (c + 1 < NCH) CP_WAIT1(); else CP_WAIT0();
        __syncthreads();                       // frees stage (c+2)%3, chunk c visible
        if (c + 2 < NCH) issue(c + 2);

        const float*    As  = smem + (c % STAGES) * (STG_BYTES / 4);
        const uint32_t* Bsu = (const uint32_t*)((const char*)As + A_BYTES);

        #pragma unroll
        for (int kk = 0; kk < 2; kk++) {       // two k16 steps per chunk
            const int ka = kk * 16 + 2 * t4;   // A k offset (floats)
            uint32_t afr[4][4], bfr[4][2];
            #pragma unroll
            for (int mi = 0; mi < 4; mi++) {
                int mr = wm * 64 + mi * 16 + g;
                float2 v0 = *(const float2*)&As[mr * LDA + ka];
                float2 v1 = *(const float2*)&As[(mr + 8) * LDA + ka];
                float2 v2 = *(const float2*)&As[mr * LDA + ka + 8];
                float2 v3 = *(const float2*)&As[(mr + 8) * LDA + ka + 8];
                afr[mi][0] = f2h2(v0.x, v0.y);
                afr[mi][1] = f2h2(v1.x, v1.y);
                afr[mi][2] = f2h2(v2.x, v2.y);
                afr[mi][3] = f2h2(v3.x, v3.y);
            }
            #pragma unroll
            for (int ni = 0; ni < 4; ni++) {
                int nc = wn * 32 + ni * 8 + g;
                bfr[ni][0] = Bsu[nc * (LDBT / 2) + kk * 8 + t4];
                bfr[ni][1] = Bsu[nc * (LDBT / 2) + kk * 8 + t4 + 4];
            }
            #pragma unroll
            for (int mi = 0; mi < 4; mi++)
                #pragma unroll
                for (int ni = 0; ni < 4; ni++)
                    mma_f16(acc[mi][ni], afr[mi], bfr[ni]);
        }
    }

    // epilogue: bias + relu -> g_feat (f16)
    #pragma unroll
    for (int mi = 0; mi < 4; mi++) {
        #pragma unroll
        for (int ni = 0; ni < 4; ni++) {
            int m = m0 + wm * 64 + mi * 16 + g;
            int n = n0 + wn * 32 + ni * 8 + 2 * t4;
            float b0 = bias[n], b1 = bias[n + 1];
            __half2 h0 = __floats2half2_rn(fmaxf(acc[mi][ni][0] + b0, 0.f),
                                           fmaxf(acc[mi][ni][1] + b1, 0.f));
            __half2 h1 = __floats2half2_rn(fmaxf(acc[mi][ni][2] + b0, 0.f),
                                           fmaxf(acc[mi][ni][3] + b1, 0.f));
            *(__half2*)&g_feat[(size_t)m * CCH + n]       = h0;
            *(__half2*)&g_feat[(size_t)(m + 8) * CCH + n] = h1;
        }
    }
}

// ---------------------------------------------------------------------------
// 2) Fused ROI align + dense. One block per 2 rois.
//    Phase A: issue first Wd stages (cp.async), bilinear-pool 2 obj rows
//             into SMEM while those loads fly.
//    Phase B: 3-stage cp.async pipeline over Wd (32 k-rows x 256 cols/stage),
//             accumulate out rows from SMEM.
// ---------------------------------------------------------------------------
#define DK        32                          // k-rows per stage
#define DNSTG     (CCH / DK)                  // 8 stages
#define DSTG_FLT  (DK * DDIM)                 // 8192 floats / stage
#define DSMEM_FLT (3 * DSTG_FLT + 2 * CCH)    // 3 stages + 2 obj rows
#define DSMEM_BYTES (DSMEM_FLT * 4)           // 100352

__global__ __launch_bounds__(256) void roi_dense_kernel(
    const float* __restrict__ boxes,   // [256, 4]
    const float* __restrict__ Wd,      // [256, 256]
    const float* __restrict__ bd,      // [256]
    float* __restrict__ out)           // [256, 256]
{
    extern __shared__ float s[];
    float* sW   = s;                          // [3][DK*DDIM]
    float* sObj = s + 3 * DSTG_FLT;           // [2][CCH]
    const uint32_t sb = smem_to_u32(s);

    const int tid = threadIdx.x;
    const int r0  = blockIdx.x * 2;

    auto issueW = [&](int st) {
        const uint32_t soff = sb + (uint32_t)(st % 3) * (DSTG_FLT * 4);
        const int k0 = st * DK;
        #pragma unroll
        for (int i = 0; i < 8; i++) {
            int f4  = tid + i * 256;           // 0..2047
            int row = f4 >> 6;                 // 0..31
            int q   = f4 & 63;                 // float4 within row
            cp16(soff + (uint32_t)(row * DDIM + q * 4) * 4,
                 Wd + (size_t)(k0 + row) * DDIM + q * 4);
        }
        CP_COMMIT();
    };

    // Kick off the first two weight stages before the roi gather.
    issueW(0); issueW(1);

    // --- Phase A: roi align for rois r0, r0+1 (channel = tid) ---
    #pragma unroll
    for (int j = 0; j < 2; j++) {
        const int roi = r0 + j;
        const int b = roi >> 4;
        float4 box = *(const float4*)&boxes[roi * 4];
        float ymin = box.x, xmin = box.y, ymax = box.z, xmax = box.w;
        bool empty = (ymin == -1.f) && (xmin == -1.f) && (ymax == -1.f) && (xmax == -1.f);
        if (empty) { sObj[j * CCH + tid] = 0.f; continue; }

        int y0[S_ROI], y1[S_ROI], x0[S_ROI], x1[S_ROI];
        float wy[S_ROI], wx[S_ROI];
        #pragma unroll
        for (int i = 0; i < S_ROI; i++) {
            float step = ((float)i + 0.5f) / (float)S_ROI;
            float ys = ymin + (ymax - ymin) * step;
            float xs = xmin + (xmax - xmin) * step;
            float py = ys * (float)FH - 0.5f;
            float px = xs * (float)FW - 0.5f;
            float y0f = floorf(py), x0f = floorf(px);
            wy[i] = py - y0f;  wx[i] = px - x0f;
            int yi = (int)y0f, xi = (int)x0f;
            y0[i] = min(max(yi, 0), FH - 1);
            y1[i] = min(max(yi + 1, 0), FH - 1);
            x0[i] = min(max(xi, 0), FW - 1);
            x1[i] = min(max(xi + 1, 0), FW - 1);
        }

        const __half* fb = g_feat + (size_t)b * FH * FW * CCH;
        float acc = 0.f;
        #pragma unroll
        for (int i = 0; i < S_ROI; i++) {
            const __half* ry0 = fb + y0[i] * (FW * CCH);
            const __half* ry1 = fb + y1[i] * (FW * CCH);
            float wyi = wy[i];
            #pragma unroll
            for (int jx = 0; jx < S_ROI; jx++) {
                float wxj = wx[jx];
                float f00 = __half2float(ry0[x0[jx] * CCH + tid]);
                float f01 = __half2float(ry0[x1[jx] * CCH + tid]);
                float f10 = __half2float(ry1[x0[jx] * CCH + tid]);
                float f11 = __half2float(ry1[x1[jx] * CCH + tid]);
                acc += (1.f - wyi) * (1.f - wxj) * f00
                     + (1.f - wyi) * wxj         * f01
                     + wyi         * (1.f - wxj) * f10
                     + wyi         * wxj         * f11;
            }
        }
        sObj[j * CCH + tid] = acc * (1.f / (S_ROI * S_ROI));
    }
    __syncthreads();    // obj rows visible to all threads

    // --- Phase B: dense pipeline ---
    float acc0 = 0.f, acc1 = 0.f;
    for (int st = 0; st < DNSTG; st++) {
        if (st + 1 < DNSTG) CP_WAIT1(); else CP_WAIT0();
        __syncthreads();                      // stage st visible; stage (st+2)%3 free
        if (st + 2 < DNSTG) issueW(st + 2);

        const float* w = sW + (st % 3) * DSTG_FLT;
        const int k0 = st * DK;
        #pragma unroll
        for (int k = 0; k < DK; k++) {
            float wv = w[k * DDIM + tid];
            acc0 += sObj[k0 + k] * wv;
            acc1 += sObj[CCH + k0 + k] * wv;
        }
    }

    float bb = bd[tid];
    out[(size_t)r0 * DDIM + tid]       = acc0 + bb;
    out[(size_t)(r0 + 1) * DDIM + tid] = acc1 + bb;
}

// ---------------------------------------------------------------------------
// Launch
// ---------------------------------------------------------------------------
extern "C" void kernel_launch(void* const* d_in, const int* in_sizes, int n_in,
                              void* d_out, int out_size) {
    const float* images  = (const float*)d_in[0];
    const float* bboxes  = (const float*)d_in[1];
    const float* conv_w  = (const float*)d_in[2];
    const float* conv_b  = (const float*)d_in[3];
    const float* dense_w = (const float*)d_in[4];
    const float* dense_b = (const float*)d_in[5];
    float* out = (float*)d_out;

    static bool attr_set = false;
    if (!attr_set) {
        cudaFuncSetAttribute(conv_mma_kernel,
                             cudaFuncAttributeMaxDynamicSharedMemorySize, SMEM_BYTES);
        cudaFuncSetAttribute(roi_dense_kernel,
                             cudaFuncAttributeMaxDynamicSharedMemorySize, DSMEM_BYTES);
        attr_set = true;
    }

    dim3 wgrid(KDIM / 32, CCH / 32);     // (24, 8)
    wprep_kernel<<<wgrid, 256>>>(conv_w);

    dim3 grid(CCH / 128, M_TOT / 128);   // (2, 128)
    conv_mma_kernel<<<grid, 256, SMEM_BYTES>>>(images, conv_b);

    roi_dense_kernel<<<(BDIM * NBOX) / 2, 256, DSMEM_BYTES>>>(
        bboxes, dense_w, dense_b, out);
}

// round 11
// speedup vs baseline: 1.0004x; 1.0004x over previous
#include <cuda_runtime.h>
#include <cuda_fp16.h>
#include <cstdint>

// ---------------------------------------------------------------------------
// Problem constants
// ---------------------------------------------------------------------------
#define BDIM   16
#define FH     32
#define FW     32
#define NBOX   16
#define CCH    256     // conv out channels
#define DDIM   256     // dense out
#define KDIM   768     // 16*16*3
#define M_TOT  16384   // B*32*32
#define S_ROI  7

// Scratch (static __device__ — no allocations allowed)
__device__ __half g_Wh[CCH * KDIM];          // W transposed+f16: [256 n][768 k]
__device__ __half g_feat[M_TOT * CCH];       // conv+relu feat [16384, 256] f16

// ---------------------------------------------------------------------------
// helpers
// ---------------------------------------------------------------------------
__device__ __forceinline__ uint32_t smem_to_u32(const void* smem_ptr) {
    uint32_t addr;
    asm("{ .reg .u64 tmp; cvta.to.shared.u64 tmp, %1; cvt.u32.u64 %0, tmp; }"
        : "=r"(addr) : "l"(smem_ptr));
    return addr;
}
__device__ __forceinline__ uint32_t f2h2(float lo, float hi) {
    uint32_t r;
    asm("cvt.rn.f16x2.f32 %0, %1, %2;" : "=r"(r) : "f"(hi), "f"(lo));
    return r;
}
__device__ __forceinline__ void mma_f16(float* d, const uint32_t* a, const uint32_t* b) {
    asm volatile(
        "mma.sync.aligned.m16n8k16.row.col.f32.f16.f16.f32 "
        "{%0,%1,%2,%3}, {%4,%5,%6,%7}, {%8,%9}, {%0,%1,%2,%3};"
        : "+f"(d[0]), "+f"(d[1]), "+f"(d[2]), "+f"(d[3])
        : "r"(a[0]), "r"(a[1]), "r"(a[2]), "r"(a[3]), "r"(b[0]), "r"(b[1]));
}
__device__ __forceinline__ void cp16(uint32_t smem_dst, const void* gsrc) {
    asm volatile("cp.async.cg.shared.global [%0], [%1], 16;"
                 :: "r"(smem_dst), "l"(gsrc));
}
#define CP_COMMIT() asm volatile("cp.async.commit_group;" ::: "memory")
#define CP_WAIT1()  asm volatile("cp.async.wait_group 1;"  ::: "memory")
#define CP_WAIT0()  asm volatile("cp.async.wait_group 0;"  ::: "memory")

// ---------------------------------------------------------------------------
// 0) W prepass: W[768,256] f32 -> g_Wh[256 n][768 k] f16 (transpose+convert)
// ---------------------------------------------------------------------------
__global__ __launch_bounds__(256) void wprep_kernel(const float* __restrict__ W) {
    __shared__ float t[32][33];
    int kb = blockIdx.x * 32, nb = blockIdx.y * 32;
    int tx = threadIdx.x & 31, ty = threadIdx.x >> 5;   // 32 x 8
    #pragma unroll
    for (int i = 0; i < 32; i += 8)
        t[ty + i][tx] = W[(kb + ty + i) * CCH + nb + tx];
    __syncthreads();
    #pragma unroll
    for (int i = 0; i < 32; i += 8)
        g_Wh[(nb + ty + i) * KDIM + kb + tx] = __float2half_rn(t[tx][ty + i]);
}

// ---------------------------------------------------------------------------
// 1) Conv-as-GEMM, fused im2col, fp16 m16n8k16 mma, 3-stage cp.async,
//    single barrier per chunk. CTA tile 128x128, 8 warps each 64x32.
// ---------------------------------------------------------------------------
#define BK      32
#define NCH     (KDIM / BK)          // 24
#define LDA     40                   // floats per A row (32 data + 8 pad)
#define LDBT    40                   // halves per B row (32 data + 8 pad)
#define A_BYTES (128 * LDA * 4)      // 20480
#define B_BYTES (128 * LDBT * 2)     // 10240
#define STG_BYTES (A_BYTES + B_BYTES)// 30720
#define STAGES  3
#define SMEM_BYTES (STAGES * STG_BYTES)   // 92160

__global__ __launch_bounds__(256, 2) void conv_mma_kernel(
    const float* __restrict__ img,     // [16,512,512,3]
    const float* __restrict__ bias)    // [256]
{
    extern __shared__ float smem[];
    const uint32_t sb = smem_to_u32(smem);

    const int tid = threadIdx.x;
    const int wid = tid >> 5;
    const int lid = tid & 31;
    const int g   = lid >> 2;          // 0..7
    const int t4  = lid & 3;           // 0..3
    const int wm  = wid & 1;           // 2 warps in M
    const int wn  = wid >> 1;          // 4 warps in N

    const int n0 = blockIdx.x * 128;
    const int m0 = blockIdx.y * 128;

    // cp.async source bases
    const float* aBase[4];
    #pragma unroll
    for (int i = 0; i < 4; i++) {
        int f4  = tid + i * 256;               // 0..1023
        int row = f4 >> 3;                     // 0..127
        int m   = m0 + row;
        int b   = m >> 10;
        int oy  = (m >> 5) & 31;
        int ox  = m & 31;
        aBase[i] = img + (size_t)((b * 512 + oy * 16) * 512 + ox * 16) * 3;
    }
    const __half* bBase[2];
    #pragma unroll
    for (int i = 0; i < 2; i++) {
        int f4  = tid + i * 256;               // 0..511
        int row = f4 >> 2;                     // 0..127
        int q   = f4 & 3;
        bBase[i] = g_Wh + (size_t)(n0 + row) * KDIM + q * 8;
    }

    auto issue = [&](int c) {
        const int k0 = c * BK;
        const uint32_t soff = sb + (uint32_t)(c % STAGES) * STG_BYTES;
        #pragma unroll
        for (int i = 0; i < 4; i++) {
            int f4  = tid + i * 256;
            int row = f4 >> 3;
            int q   = f4 & 7;
            int k   = k0 + q * 4;
            int ky  = k / 48;
            int rem = k - ky * 48;             // 4 | 48 -> never crosses pixel run
            cp16(soff + (uint32_t)(row * (LDA * 4) + q * 16),
                 aBase[i] + ky * 1536 + rem);
        }
        #pragma unroll
        for (int i = 0; i < 2; i++) {
            int f4  = tid + i * 256;
            int row = f4 >> 2;
            int q   = f4 & 3;
            cp16(soff + (uint32_t)(A_BYTES + row * (LDBT * 2) + q * 16),
                 bBase[i] + k0);
        }
        CP_COMMIT();
    };

    float acc[4][4][4];
    #pragma unroll
    for (int i = 0; i < 4; i++)
        #pragma unroll
        for (int j = 0; j < 4; j++)
            #pragma unroll
            for (int r = 0; r < 4; r++) acc[i][j][r] = 0.f;

    // prologue: 2 chunks in flight
    issue(0); issue(1);

    for (int c = 0; c < NCH; c++) {
        if (c + 1 < NCH) CP_WAIT1(); else CP_WAIT0();
        __syncthreads();                       // frees stage (c+2)%3, chunk c visible
        if (c + 2 < NCH) issue(c + 2);

        const float*    As  = smem + (c % STAGES) * (STG_BYTES / 4);
        const uint32_t* Bsu = (const uint32_t*)((const char*)As + A_BYTES);

        #pragma unroll
        for (int kk = 0; kk < 2; kk++) {       // two k16 steps per chunk
            const int ka = kk * 16 + 2 * t4;   // A k offset (floats)
            uint32_t afr[4][4], bfr[4][2];
            #pragma unroll
            for (int mi = 0; mi < 4; mi++) {
                int mr = wm * 64 + mi * 16 + g;
                float2 v0 = *(const float2*)&As[mr * LDA + ka];
                float2 v1 = *(const float2*)&As[(mr + 8) * LDA + ka];
                float2 v2 = *(const float2*)&As[mr * LDA + ka + 8];
                float2 v3 = *(const float2*)&As[(mr + 8) * LDA + ka + 8];
                afr[mi][0] = f2h2(v0.x, v0.y);
                afr[mi][1] = f2h2(v1.x, v1.y);
                afr[mi][2] = f2h2(v2.x, v2.y);
                afr[mi][3] = f2h2(v3.x, v3.y);
            }
            #pragma unroll
            for (int ni = 0; ni < 4; ni++) {
                int nc = wn * 32 + ni * 8 + g;
                bfr[ni][0] = Bsu[nc * (LDBT / 2) + kk * 8 + t4];
                bfr[ni][1] = Bsu[nc * (LDBT / 2) + kk * 8 + t4 + 4];
            }
            #pragma unroll
            for (int mi = 0; mi < 4; mi++)
                #pragma unroll
                for (int ni = 0; ni < 4; ni++)
                    mma_f16(acc[mi][ni], afr[mi], bfr[ni]);
        }
    }

    // epilogue: bias + relu -> g_feat (f16)
    #pragma unroll
    for (int mi = 0; mi < 4; mi++) {
        #pragma unroll
        for (int ni = 0; ni < 4; ni++) {
            int m = m0 + wm * 64 + mi * 16 + g;
            int n = n0 + wn * 32 + ni * 8 + 2 * t4;
            float b0 = bias[n], b1 = bias[n + 1];
            __half2 h0 = __floats2half2_rn(fmaxf(acc[mi][ni][0] + b0, 0.f),
                                           fmaxf(acc[mi][ni][1] + b1, 0.f));
            __half2 h1 = __floats2half2_rn(fmaxf(acc[mi][ni][2] + b0, 0.f),
                                           fmaxf(acc[mi][ni][3] + b1, 0.f));
            *(__half2*)&g_feat[(size_t)m * CCH + n]       = h0;
            *(__half2*)&g_feat[(size_t)(m + 8) * CCH + n] = h1;
        }
    }
}

// ---------------------------------------------------------------------------
// 2) Fused ROI align + dense. One block per 2 rois.
//    Phase A: issue first Wd stages (cp.async), bilinear-pool 2 obj rows
//             into SMEM while those loads fly.
//    Phase B: 3-stage cp.async pipeline over Wd (32 k-rows x 256 cols/stage),
//             accumulate out rows from SMEM.
// ---------------------------------------------------------------------------
#define DK        32                          // k-rows per stage
#define DNSTG     (CCH / DK)                  // 8 stages
#define DSTG_FLT  (DK * DDIM)                 // 8192 floats / stage
#define DSMEM_FLT (3 * DSTG_FLT + 2 * CCH)    // 3 stages + 2 obj rows
#define DSMEM_BYTES (DSMEM_FLT * 4)           // 100352

__global__ __launch_bounds__(256) void roi_dense_kernel(
    const float* __restrict__ boxes,   // [256, 4]
    const float* __restrict__ Wd,      // [256, 256]
    const float* __restrict__ bd,      // [256]
    float* __restrict__ out)           // [256, 256]
{
    extern __shared__ float s[];
    float* sW   = s;                          // [3][DK*DDIM]
    float* sObj = s + 3 * DSTG_FLT;           // [2][CCH]
    const uint32_t sb = smem_to_u32(s);

    const int tid = threadIdx.x;
    const int r0  = blockIdx.x * 2;

    auto issueW = [&](int st) {
        const uint32_t soff = sb + (uint32_t)(st % 3) * (DSTG_FLT * 4);
        const int k0 = st * DK;
        #pragma unroll
        for (int i = 0; i < 8; i++) {
            int f4  = tid + i * 256;           // 0..2047
            int row = f4 >> 6;                 // 0..31
            int q   = f4 & 63;                 // float4 within row
            cp16(soff + (uint32_t)(row * DDIM + q * 4) * 4,
                 Wd + (size_t)(k0 + row) * DDIM + q * 4);
        }
        CP_COMMIT();
    };

    // Kick off the first two weight stages before the roi gather.
    issueW(0); issueW(1);

    const float bb = bd[tid];   // hoisted off the output critical path

    // --- Phase A: roi align for rois r0, r0+1 (channel = tid) ---
    #pragma unroll
    for (int j = 0; j < 2; j++) {
        const int roi = r0 + j;
        const int b = roi >> 4;
        float4 box = *(const float4*)&boxes[roi * 4];
        float ymin = box.x, xmin = box.y, ymax = box.z, xmax = box.w;
        bool empty = (ymin == -1.f) && (xmin == -1.f) && (ymax == -1.f) && (xmax == -1.f);
        if (empty) { sObj[j * CCH + tid] = 0.f; continue; }

        int y0[S_ROI], y1[S_ROI], x0[S_ROI], x1[S_ROI];
        float wy[S_ROI], wx[S_ROI];
        #pragma unroll
        for (int i = 0; i < S_ROI; i++) {
            float step = ((float)i + 0.5f) / (float)S_ROI;
            float ys = ymin + (ymax - ymin) * step;
            float xs = xmin + (xmax - xmin) * step;
            float py = ys * (float)FH - 0.5f;
            float px = xs * (float)FW - 0.5f;
            float y0f = floorf(py), x0f = floorf(px);
            wy[i] = py - y0f;  wx[i] = px - x0f;
            int yi = (int)y0f, xi = (int)x0f;
            y0[i] = min(max(yi, 0), FH - 1);
            y1[i] = min(max(yi + 1, 0), FH - 1);
            x0[i] = min(max(xi, 0), FW - 1);
            x1[i] = min(max(xi + 1, 0), FW - 1);
        }

        const __half* fb = g_feat + (size_t)b * FH * FW * CCH;
        float acc = 0.f;
        #pragma unroll
        for (int i = 0; i < S_ROI; i++) {
            const __half* ry0 = fb + y0[i] * (FW * CCH);
            const __half* ry1 = fb + y1[i] * (FW * CCH);
            float wyi = wy[i];
            #pragma unroll
            for (int jx = 0; jx < S_ROI; jx++) {
                float wxj = wx[jx];
                float f00 = __half2float(ry0[x0[jx] * CCH + tid]);
                float f01 = __half2float(ry0[x1[jx] * CCH + tid]);
                float f10 = __half2float(ry1[x0[jx] * CCH + tid]);
                float f11 = __half2float(ry1[x1[jx] * CCH + tid]);
                acc += (1.f - wyi) * (1.f - wxj) * f00
                     + (1.f - wyi) * wxj         * f01
                     + wyi         * (1.f - wxj) * f10
                     + wyi         * wxj         * f11;
            }
        }
        sObj[j * CCH + tid] = acc * (1.f / (S_ROI * S_ROI));
    }
    __syncthreads();    // obj rows visible to all threads

    // --- Phase B: dense pipeline ---
    float acc0 = 0.f, acc1 = 0.f;
    for (int st = 0; st < DNSTG; st++) {
        if (st + 1 < DNSTG) CP_WAIT1(); else CP_WAIT0();
        __syncthreads();                      // stage st visible; stage (st+2)%3 free
        if (st + 2 < DNSTG) issueW(st + 2);

        const float* w = sW + (st % 3) * DSTG_FLT;
        const int k0 = st * DK;
        #pragma unroll
        for (int k = 0; k < DK; k++) {
            float wv = w[k * DDIM + tid];
            acc0 += sObj[k0 + k] * wv;
            acc1 += sObj[CCH + k0 + k] * wv;
        }
    }

    out[(size_t)r0 * DDIM + tid]       = acc0 + bb;
    out[(size_t)(r0 + 1) * DDIM + tid] = acc1 + bb;
}

// ---------------------------------------------------------------------------
// Launch
// ---------------------------------------------------------------------------
extern "C" void kernel_launch(void* const* d_in, const int* in_sizes, int n_in,
                              void* d_out, int out_size) {
    const float* images  = (const float*)d_in[0];
    const float* bboxes  = (const float*)d_in[1];
    const float* conv_w  = (const float*)d_in[2];
    const float* conv_b  = (const float*)d_in[3];
    const float* dense_w = (const float*)d_in[4];
    const float* dense_b = (const float*)d_in[5];
    float* out = (float*)d_out;

    static bool attr_set = false;
    if (!attr_set) {
        cudaFuncSetAttribute(conv_mma_kernel,
                             cudaFuncAttributeMaxDynamicSharedMemorySize, SMEM_BYTES);
        cudaFuncSetAttribute(roi_dense_kernel,
                             cudaFuncAttributeMaxDynamicSharedMemorySize, DSMEM_BYTES);
        attr_set = true;
    }

    dim3 wgrid(KDIM / 32, CCH / 32);     // (24, 8)
    wprep_kernel<<<wgrid, 256>>>(conv_w);

    dim3 grid(CCH / 128, M_TOT / 128);   // (2, 128)
    conv_mma_kernel<<<grid, 256, SMEM_BYTES>>>(images, conv_b);

    roi_dense_kernel<<<(BDIM * NBOX) / 2, 256, DSMEM_BYTES>>>(
        bboxes, dense_w, dense_b, out);
}

// round 12
// speedup vs baseline: 1.1534x; 1.1530x over previous
#include <cuda_runtime.h>
#include <cuda_fp16.h>
#include <cstdint>

// ---------------------------------------------------------------------------
// Problem constants
// ---------------------------------------------------------------------------
#define BDIM   16
#define FH     32
#define FW     32
#define NBOX   16
#define CCH    256     // conv out channels
#define DDIM   256     // dense out
#define KDIM   768     // 16*16*3
#define M_TOT  16384   // B*32*32
#define S_ROI  7

// Scratch (static __device__ — no allocations allowed)
__device__ __half g_Wh[CCH * KDIM];          // W transposed+f16: [256 n][768 k]
__device__ __half g_feat[M_TOT * CCH];       // conv+relu feat [16384, 256] f16
__device__ float  g_obj[BDIM * NBOX * CCH];  // pooled rois   [256, 256]

// ---------------------------------------------------------------------------
// helpers
// ---------------------------------------------------------------------------
__device__ __forceinline__ uint32_t smem_to_u32(const void* smem_ptr) {
    uint32_t addr;
    asm("{ .reg .u64 tmp; cvta.to.shared.u64 tmp, %1; cvt.u32.u64 %0, tmp; }"
        : "=r"(addr) : "l"(smem_ptr));
    return addr;
}
__device__ __forceinline__ uint32_t f2h2(float lo, float hi) {
    uint32_t r;
    asm("cvt.rn.f16x2.f32 %0, %1, %2;" : "=r"(r) : "f"(hi), "f"(lo));
    return r;
}
__device__ __forceinline__ void mma_f16(float* d, const uint32_t* a, const uint32_t* b) {
    asm volatile(
        "mma.sync.aligned.m16n8k16.row.col.f32.f16.f16.f32 "
        "{%0,%1,%2,%3}, {%4,%5,%6,%7}, {%8,%9}, {%0,%1,%2,%3};"
        : "+f"(d[0]), "+f"(d[1]), "+f"(d[2]), "+f"(d[3])
        : "r"(a[0]), "r"(a[1]), "r"(a[2]), "r"(a[3]), "r"(b[0]), "r"(b[1]));
}
__device__ __forceinline__ void cp16(uint32_t smem_dst, const void* gsrc) {
    asm volatile("cp.async.cg.shared.global [%0], [%1], 16;"
                 :: "r"(smem_dst), "l"(gsrc));
}
#define CP_COMMIT() asm volatile("cp.async.commit_group;" ::: "memory")
#define CP_WAIT1()  asm volatile("cp.async.wait_group 1;"  ::: "memory")
#define CP_WAIT0()  asm volatile("cp.async.wait_group 0;"  ::: "memory")

// ---------------------------------------------------------------------------
// 0) W prepass: W[768,256] f32 -> g_Wh[256 n][768 k] f16 (transpose+convert)
// ---------------------------------------------------------------------------
__global__ __launch_bounds__(256) void wprep_kernel(const float* __restrict__ W) {
    __shared__ float t[32][33];
    int kb = blockIdx.x * 32, nb = blockIdx.y * 32;
    int tx = threadIdx.x & 31, ty = threadIdx.x >> 5;   // 32 x 8
    #pragma unroll
    for (int i = 0; i < 32; i += 8)
        t[ty + i][tx] = W[(kb + ty + i) * CCH + nb + tx];
    __syncthreads();
    #pragma unroll
    for (int i = 0; i < 32; i += 8)
        g_Wh[(nb + ty + i) * KDIM + kb + tx] = __float2half_rn(t[tx][ty + i]);
}

// ---------------------------------------------------------------------------
// 1) Conv-as-GEMM, fused im2col, fp16 m16n8k16 mma, 3-stage cp.async,
//    single barrier per chunk. CTA tile 128x128, 8 warps each 64x32.
// ---------------------------------------------------------------------------
#define BK      32
#define NCH     (KDIM / BK)          // 24
#define LDA     40                   // floats per A row (32 data + 8 pad)
#define LDBT    40                   // halves per B row (32 data + 8 pad)
#define A_BYTES (128 * LDA * 4)      // 20480
#define B_BYTES (128 * LDBT * 2)     // 10240
#define STG_BYTES (A_BYTES + B_BYTES)// 30720
#define STAGES  3
#define SMEM_BYTES (STAGES * STG_BYTES)   // 92160

__global__ __launch_bounds__(256, 2) void conv_mma_kernel(
    const float* __restrict__ img,     // [16,512,512,3]
    const float* __restrict__ bias)    // [256]
{
    extern __shared__ float smem[];
    const uint32_t sb = smem_to_u32(smem);

    const int tid = threadIdx.x;
    const int wid = tid >> 5;
    const int lid = tid & 31;
    const int g   = lid >> 2;          // 0..7
    const int t4  = lid & 3;           // 0..3
    const int wm  = wid & 1;           // 2 warps in M
    const int wn  = wid >> 1;          // 4 warps in N

    const int n0 = blockIdx.x * 128;
    const int m0 = blockIdx.y * 128;

    // cp.async source bases
    const float* aBase[4];
    #pragma unroll
    for (int i = 0; i < 4; i++) {
        int f4  = tid + i * 256;               // 0..1023
        int row = f4 >> 3;                     // 0..127
        int m   = m0 + row;
        int b   = m >> 10;
        int oy  = (m >> 5) & 31;
        int ox  = m & 31;
        aBase[i] = img + (size_t)((b * 512 + oy * 16) * 512 + ox * 16) * 3;
    }
    const __half* bBase[2];
    #pragma unroll
    for (int i = 0; i < 2; i++) {
        int f4  = tid + i * 256;               // 0..511
        int row = f4 >> 2;                     // 0..127
        int q   = f4 & 3;
        bBase[i] = g_Wh + (size_t)(n0 + row) * KDIM + q * 8;
    }

    auto issue = [&](int c) {
        const int k0 = c * BK;
        const uint32_t soff = sb + (uint32_t)(c % STAGES) * STG_BYTES;
        #pragma unroll
        for (int i = 0; i < 4; i++) {
            int f4  = tid + i * 256;
            int row = f4 >> 3;
            int q   = f4 & 7;
            int k   = k0 + q * 4;
            int ky  = k / 48;
            int rem = k - ky * 48;             // 4 | 48 -> never crosses pixel run
            cp16(soff + (uint32_t)(row * (LDA * 4) + q * 16),
                 aBase[i] + ky * 1536 + rem);
        }
        #pragma unroll
        for (int i = 0; i < 2; i++) {
            int f4  = tid + i * 256;
            int row = f4 >> 2;
            int q   = f4 & 3;
            cp16(soff + (uint32_t)(A_BYTES + row * (LDBT * 2) + q * 16),
                 bBase[i] + k0);
        }
        CP_COMMIT();
    };

    float acc[4][4][4];
    #pragma unroll
    for (int i = 0; i < 4; i++)
        #pragma unroll
        for (int j = 0; j < 4; j++)
            #pragma unroll
            for (int r = 0; r < 4; r++) acc[i][j][r] = 0.f;

    // prologue: 2 chunks in flight
    issue(0); issue(1);

    for (int c = 0; c < NCH; c++) {
        if (c + 1 < NCH) CP_WAIT1(); else CP_WAIT0();
        __syncthreads();                       // frees stage (c+2)%3, chunk c visible
        if (c + 2 < NCH) issue(c + 2);

        const float*    As  = smem + (c % STAGES) * (STG_BYTES / 4);
        const uint32_t* Bsu = (const uint32_t*)((const char*)As + A_BYTES);

        #pragma unroll
        for (int kk = 0; kk < 2; kk++) {       // two k16 steps per chunk
            const int ka = kk * 16 + 2 * t4;   // A k offset (floats)
            uint32_t afr[4][4], bfr[4][2];
            #pragma unroll
            for (int mi = 0; mi < 4; mi++) {
                int mr = wm * 64 + mi * 16 + g;
                float2 v0 = *(const float2*)&As[mr * LDA + ka];
                float2 v1 = *(const float2*)&As[(mr + 8) * LDA + ka];
                float2 v2 = *(const float2*)&As[mr * LDA + ka + 8];
                float2 v3 = *(const float2*)&As[(mr + 8) * LDA + ka + 8];
                afr[mi][0] = f2h2(v0.x, v0.y);
                afr[mi][1] = f2h2(v1.x, v1.y);
                afr[mi][2] = f2h2(v2.x, v2.y);
                afr[mi][3] = f2h2(v3.x, v3.y);
            }
            #pragma unroll
            for (int ni = 0; ni < 4; ni++) {
                int nc = wn * 32 + ni * 8 + g;
                bfr[ni][0] = Bsu[nc * (LDBT / 2) + kk * 8 + t4];
                bfr[ni][1] = Bsu[nc * (LDBT / 2) + kk * 8 + t4 + 4];
            }
            #pragma unroll
            for (int mi = 0; mi < 4; mi++)
                #pragma unroll
                for (int ni = 0; ni < 4; ni++)
                    mma_f16(acc[mi][ni], afr[mi], bfr[ni]);
        }
    }

    // epilogue: bias + relu -> g_feat (f16)
    #pragma unroll
    for (int mi = 0; mi < 4; mi++) {
        #pragma unroll
        for (int ni = 0; ni < 4; ni++) {
            int m = m0 + wm * 64 + mi * 16 + g;
            int n = n0 + wn * 32 + ni * 8 + 2 * t4;
            float b0 = bias[n], b1 = bias[n + 1];
            __half2 h0 = __floats2half2_rn(fmaxf(acc[mi][ni][0] + b0, 0.f),
                                           fmaxf(acc[mi][ni][1] + b1, 0.f));
            __half2 h1 = __floats2half2_rn(fmaxf(acc[mi][ni][2] + b0, 0.f),
                                           fmaxf(acc[mi][ni][3] + b1, 0.f));
            *(__half2*)&g_feat[(size_t)m * CCH + n]       = h0;
            *(__half2*)&g_feat[(size_t)(m + 8) * CCH + n] = h1;
        }
    }
}

// ---------------------------------------------------------------------------
// 2) ROI align (bilinear, 7x7) + mean + notrack mask. 256 blocks (1 roi each).
// ---------------------------------------------------------------------------
__global__ __launch_bounds__(256) void roi_kernel(const float* __restrict__ boxes) {
    const int roi = blockIdx.x;
    const int b = roi >> 4;
    const int c = threadIdx.x;

    float4 box = *(const float4*)&boxes[roi * 4];
    float ymin = box.x, xmin = box.y, ymax = box.z, xmax = box.w;
    bool empty = (ymin == -1.f) && (xmin == -1.f) && (ymax == -1.f) && (xmax == -1.f);
    if (empty) { g_obj[roi * CCH + c] = 0.f; return; }

    int y0[S_ROI], y1[S_ROI], x0[S_ROI], x1[S_ROI];
    float wy[S_ROI], wx[S_ROI];
    #pragma unroll
    for (int i = 0; i < S_ROI; i++) {
        float step = ((float)i + 0.5f) / (float)S_ROI;
        float ys = ymin + (ymax - ymin) * step;
        float xs = xmin + (xmax - xmin) * step;
        float py = ys * (float)FH - 0.5f;
        float px = xs * (float)FW - 0.5f;
        float y0f = floorf(py), x0f = floorf(px);
        wy[i] = py - y0f;  wx[i] = px - x0f;
        int yi = (int)y0f, xi = (int)x0f;
        y0[i] = min(max(yi, 0), FH - 1);
        y1[i] = min(max(yi + 1, 0), FH - 1);
        x0[i] = min(max(xi, 0), FW - 1);
        x1[i] = min(max(xi + 1, 0), FW - 1);
    }

    const __half* fb = g_feat + (size_t)b * FH * FW * CCH;
    float acc = 0.f;
    #pragma unroll
    for (int i = 0; i < S_ROI; i++) {
        const __half* ry0 = fb + y0[i] * (FW * CCH);
        const __half* ry1 = fb + y1[i] * (FW * CCH);
        float wyi = wy[i];
        #pragma unroll
        for (int j = 0; j < S_ROI; j++) {
            float wxj = wx[j];
            float f00 = __half2float(ry0[x0[j] * CCH + c]);
            float f01 = __half2float(ry0[x1[j] * CCH + c]);
            float f10 = __half2float(ry1[x0[j] * CCH + c]);
            float f11 = __half2float(ry1[x1[j] * CCH + c]);
            acc += (1.f - wyi) * (1.f - wxj) * f00
                 + (1.f - wyi) * wxj         * f01
                 + wyi         * (1.f - wxj) * f10
                 + wyi         * wxj         * f11;
        }
    }
    g_obj[roi * CCH + c] = acc * (1.f / (S_ROI * S_ROI));
}

// ---------------------------------------------------------------------------
// 3) Dense: out[256,256] = obj[256,256] @ Wd[256,256] + bd.
//    128 blocks x 2 rows. Wd streamed via 3-stage cp.async pipeline
//    (immune to register-pressure MLP collapse that capped the
//     register-prefetch version at 14.4us).
// ---------------------------------------------------------------------------
#define DK        32                          // k-rows per stage
#define DNSTG     (CCH / DK)                  // 8 stages
#define DSTG_FLT  (DK * DDIM)                 // 8192 floats / stage
#define DSMEM_BYTES ((3 * DSTG_FLT + 2 * CCH) * 4)   // 100352

__global__ __launch_bounds__(256) void dense_kernel(
    const float* __restrict__ Wd, const float* __restrict__ bd,
    float* __restrict__ out)
{
    extern __shared__ float s[];
    float* sW   = s;                          // [3][DK*DDIM]
    float* sObj = s + 3 * DSTG_FLT;           // [2][CCH]
    const uint32_t sb = smem_to_u32(s);

    const int tid = threadIdx.x;
    const int r0  = blockIdx.x * 2;

    auto issueW = [&](int st) {
        const uint32_t soff = sb + (uint32_t)(st % 3) * (DSTG_FLT * 4);
        const int k0 = st * DK;
        #pragma unroll
        for (int i = 0; i < 8; i++) {
            int f4  = tid + i * 256;           // 0..2047
            int row = f4 >> 6;                 // 0..31
            int q   = f4 & 63;
            cp16(soff + (uint32_t)(row * DDIM + q * 4) * 4,
                 Wd + (size_t)(k0 + row) * DDIM + q * 4);
        }
        CP_COMMIT();
    };

    issueW(0); issueW(1);

    sObj[tid]       = g_obj[(size_t)r0 * CCH + tid];
    sObj[CCH + tid] = g_obj[(size_t)(r0 + 1) * CCH + tid];
    const float bb = bd[tid];
    __syncthreads();

    float acc0 = 0.f, acc1 = 0.f;
    for (int st = 0; st < DNSTG; st++) {
        if (st + 1 < DNSTG) CP_WAIT1(); else CP_WAIT0();
        __syncthreads();                      // stage st visible; stage (st+2)%3 free
        if (st + 2 < DNSTG) issueW(st + 2);

        const float* w = sW + (st % 3) * DSTG_FLT;
        const int k0 = st * DK;
        #pragma unroll
        for (int k = 0; k < DK; k++) {
            float wv = w[k * DDIM + tid];
            acc0 += sObj[k0 + k] * wv;
            acc1 += sObj[CCH + k0 + k] * wv;
        }
    }

    out[(size_t)r0 * DDIM + tid]       = acc0 + bb;
    out[(size_t)(r0 + 1) * DDIM + tid] = acc1 + bb;
}

// ---------------------------------------------------------------------------
// Launch
// ---------------------------------------------------------------------------
extern "C" void kernel_launch(void* const* d_in, const int* in_sizes, int n_in,
                              void* d_out, int out_size) {
    const float* images  = (const float*)d_in[0];
    const float* bboxes  = (const float*)d_in[1];
    const float* conv_w  = (const float*)d_in[2];
    const float* conv_b  = (const float*)d_in[3];
    const float* dense_w = (const float*)d_in[4];
    const float* dense_b = (const float*)d_in[5];
    float* out = (float*)d_out;

    static bool attr_set = false;
    if (!attr_set) {
        cudaFuncSetAttribute(conv_mma_kernel,
                             cudaFuncAttributeMaxDynamicSharedMemorySize, SMEM_BYTES);
        cudaFuncSetAttribute(dense_kernel,
                             cudaFuncAttributeMaxDynamicSharedMemorySize, DSMEM_BYTES);
        attr_set = true;
    }

    dim3 wgrid(KDIM / 32, CCH / 32);     // (24, 8)
    wprep_kernel<<<wgrid, 256>>>(conv_w);

    dim3 grid(CCH / 128, M_TOT / 128);   // (2, 128)
    conv_mma_kernel<<<grid, 256, SMEM_BYTES>>>(images, conv_b);

    roi_kernel<<<BDIM * NBOX, CCH>>>(bboxes);

    dense_kernel<<<(BDIM * NBOX) / 2, 256, DSMEM_BYTES>>>(dense_w, dense_b, out);
}